// round 15
// baseline (speedup 1.0000x reference)
#include <cuda_runtime.h>
#include <cuda_bf16.h>
#include <cuda_fp16.h>
#include <math.h>
#include <cstdint>

constexpr int S = 4096, HID = 2048, HQ = 16, HKV = 8, D = 128, WINDOW = 1024;

// fp16 operands
__device__ __half g_hh[(size_t)S * HID];
__device__ __half g_wqkv[(size_t)(HQ + 2 * HKV) * D * HID];   // [4096, 2048]
__device__ __half g_wo[(size_t)HID * HQ * D];
__device__ __half g_ah[(size_t)S * HQ * D];
__device__ __half g_qf[(size_t)S * HQ * D];
__device__ __half g_kf[(size_t)S * HKV * D];
__device__ __half g_vf[(size_t)S * HKV * D];

// ---------------------------------------------------------------------------
__device__ __forceinline__ uint32_t smem_u32(const void* p) {
    uint32_t a;
    asm("{ .reg .u64 t; cvta.to.shared.u64 t, %1; cvt.u32.u64 %0, t; }" : "=r"(a) : "l"(p));
    return a;
}
__device__ __forceinline__ uint32_t swz(uint32_t o) { return o ^ ((o >> 3) & 0x70); }
__device__ __forceinline__ uint32_t sw256(int r, int c) {
    return (uint32_t)(r * 256 + (((c ^ r) & 7) << 4) + ((c & 8) << 4));
}

#define CP_ASYNC16(dst, src) \
    asm volatile("cp.async.cg.shared.global [%0], [%1], 16;" :: "r"(dst), "l"(src))
#define CP_COMMIT() asm volatile("cp.async.commit_group;" ::: "memory")
#define CP_WAIT2()  asm volatile("cp.async.wait_group 2;" ::: "memory")
#define CP_WAIT1()  asm volatile("cp.async.wait_group 1;" ::: "memory")
#define CP_WAIT0()  asm volatile("cp.async.wait_group 0;" ::: "memory")

#define LDSM_X4(r0, r1, r2, r3, addr) \
    asm volatile("ldmatrix.sync.aligned.m8n8.x4.shared.b16 {%0,%1,%2,%3}, [%4];" \
                 : "=r"(r0), "=r"(r1), "=r"(r2), "=r"(r3) : "r"(addr))
#define LDSM_X4_T(r0, r1, r2, r3, addr) \
    asm volatile("ldmatrix.sync.aligned.m8n8.x4.trans.shared.b16 {%0,%1,%2,%3}, [%4];" \
                 : "=r"(r0), "=r"(r1), "=r"(r2), "=r"(r3) : "r"(addr))

#define MMA_F16(d, a, b) \
    asm volatile("mma.sync.aligned.m16n8k16.row.col.f32.f16.f16.f32 " \
                 "{%0,%1,%2,%3},{%4,%5,%6,%7},{%8,%9},{%0,%1,%2,%3};" \
                 : "+f"((d)[0]), "+f"((d)[1]), "+f"((d)[2]), "+f"((d)[3]) \
                 : "r"((a)[0]), "r"((a)[1]), "r"((a)[2]), "r"((a)[3]), \
                   "r"((b)[0]), "r"((b)[1]))

__device__ __forceinline__ uint32_t pack_h2(float a, float b) {
    __half2 t = __floats2half2_rn(a, b);
    return *(uint32_t*)&t;
}

// ---------------------------------------------------------------------------
// Single merged fp32->fp16 convert over all 5 tensors.
// ---------------------------------------------------------------------------
constexpr int CB_H  = 8192;
constexpr int CB_WQ = CB_H  + 4096;
constexpr int CB_WK = CB_WQ + 2048;
constexpr int CB_WV = CB_WK + 2048;
constexpr int CB_TOTAL = CB_WV + 4096;      // 20480 blocks

__global__ __launch_bounds__(256)
void conv_all(const float* __restrict__ hidden, const float* __restrict__ Wq,
              const float* __restrict__ Wk, const float* __restrict__ Wv,
              const float* __restrict__ Wo,
              __half* __restrict__ hh, __half* __restrict__ wqkv, __half* __restrict__ wo) {
    const int b = blockIdx.x;
    const float* src;
    __half* dst;
    int rel;
    if (b < CB_H)        { src = hidden; dst = hh;                          rel = b; }
    else if (b < CB_WQ)  { src = Wq;     dst = wqkv;                        rel = b - CB_H; }
    else if (b < CB_WK)  { src = Wk;     dst = wqkv + (size_t)HQ * D * HID; rel = b - CB_WQ; }
    else if (b < CB_WV)  { src = Wv;     dst = wqkv + (size_t)(HQ + HKV) * D * HID; rel = b - CB_WK; }
    else                 { src = Wo;     dst = wo;                          rel = b - CB_WV; }
    int i = (rel * 256 + threadIdx.x) * 4;
    float4 v = *(const float4*)(src + i);
    *(__half2*)(dst + i)     = __floats2half2_rn(v.x, v.y);
    *(__half2*)(dst + i + 2) = __floats2half2_rn(v.z, v.w);
}

// ---------------------------------------------------------------------------
// fp16 GEMM with fused epilogues, 3-stage cp.async pipeline.
// ---------------------------------------------------------------------------
constexpr int TILE_BYTES = 128 * 64 * 2;
constexpr int BUF_BYTES  = 2 * TILE_BYTES;
constexpr int NSTAGE     = 3;
constexpr int XT_STRIDE  = 132;
constexpr int GEMM_SMEM  = NSTAGE * BUF_BYTES;

template<int MODE>
__global__ __launch_bounds__(256, 2)
void gemm_fused(const __half* __restrict__ A, const __half* __restrict__ B,
                float* __restrict__ Cf,
                __half* __restrict__ qf_o, __half* __restrict__ kf_o, __half* __restrict__ vf_o,
                const float* __restrict__ qw, const float* __restrict__ kw,
                const float* __restrict__ cosp, const float* __restrict__ sinp,
                int N, int K) {
    extern __shared__ char smem[];
    const uint32_t sb = smem_u32(smem);
    const int tid = threadIdx.x;
    const int wid = tid >> 5;
    const int lane = tid & 31;
    const int wm = wid >> 2;
    const int wn = wid & 3;
    const int bm = blockIdx.y * 128;
    const int bn = blockIdx.x * 128;

    const __half* srcs[2] = { A, B };
    const int row0s[2] = { bm, bn };

    auto issue_copy = [&](int c) {
        const uint32_t base = sb + (uint32_t)(c % NSTAGE) * BUF_BYTES;
        const int k0 = c << 6;
#pragma unroll
        for (int t = 0; t < 2; t++) {
            const __half* src = srcs[t];
            const int row0 = row0s[t];
            const uint32_t tbase = base + t * TILE_BYTES;
#pragma unroll
            for (int i = 0; i < 4; i++) {
                int idx = tid + i * 256;
                int r  = idx >> 3;
                int cc = idx & 7;
                uint32_t dst = tbase + swz((uint32_t)(r * 128 + cc * 16));
                const void* s = src + (size_t)(row0 + r) * K + k0 + cc * 8;
                CP_ASYNC16(dst, s);
            }
        }
        CP_COMMIT();
    };

    float acc[4][4][4];
#pragma unroll
    for (int a = 0; a < 4; a++)
#pragma unroll
        for (int b = 0; b < 4; b++)
#pragma unroll
            for (int x = 0; x < 4; x++) acc[a][b][x] = 0.f;

    const int arow = (lane & 15);
    const int ahi  = lane >> 4;
    uint32_t a_rowoff[4];
#pragma unroll
    for (int mf = 0; mf < 4; mf++)
        a_rowoff[mf] = (uint32_t)((wm * 64 + mf * 16 + arow) * 128);
    const uint32_t arx = (uint32_t)(arow & 7);

    const int bnrow = (lane & 7) + ((lane >> 4) & 1) * 8;
    const int bhi   = (lane >> 3) & 1;
    uint32_t b_rowoff[2];
#pragma unroll
    for (int bf = 0; bf < 2; bf++)
        b_rowoff[bf] = (uint32_t)((wn * 32 + bf * 16 + bnrow) * 128);
    const uint32_t brx = (uint32_t)(bnrow & 7);

    const int NC = K >> 6;
    issue_copy(0);
    if (NC > 1) issue_copy(1);
    if (NC > 2) issue_copy(2);

    for (int c = 0; c < NC; c++) {
        if (c + 3 <= NC)      { CP_WAIT2(); }
        else if (c + 2 <= NC) { CP_WAIT1(); }
        else                  { CP_WAIT0(); }
        __syncthreads();

        const uint32_t base = sb + (uint32_t)(c % NSTAGE) * BUF_BYTES;
        const uint32_t A_b = base;
        const uint32_t B_b = base + TILE_BYTES;

#pragma unroll
        for (int ks = 0; ks < 4; ks++) {
            uint32_t ah[4][4], bh[2][4];
            const uint32_t ac = (uint32_t)(ks * 2 + ahi);
            const uint32_t bc = (uint32_t)(ks * 2 + bhi);
#pragma unroll
            for (int mf = 0; mf < 4; mf++) {
                uint32_t off = a_rowoff[mf] + ((ac ^ arx) << 4);
                LDSM_X4(ah[mf][0], ah[mf][1], ah[mf][2], ah[mf][3], A_b + off);
            }
#pragma unroll
            for (int bf = 0; bf < 2; bf++) {
                uint32_t off = b_rowoff[bf] + ((bc ^ brx) << 4);
                LDSM_X4(bh[bf][0], bh[bf][1], bh[bf][2], bh[bf][3], B_b + off);
            }
#pragma unroll
            for (int mf = 0; mf < 4; mf++)
#pragma unroll
                for (int nf = 0; nf < 4; nf++) {
                    MMA_F16(acc[mf][nf], ah[mf], (&bh[nf >> 1][(nf & 1) * 2]));
                }
        }
        __syncthreads();
        if (c + NSTAGE < NC) issue_copy(c + NSTAGE);
    }

    const int er = lane >> 2;
    const int ec = (lane & 3) * 2;

    if (MODE == 0) {
#pragma unroll
        for (int mf = 0; mf < 4; mf++) {
            const int r0 = bm + wm * 64 + mf * 16 + er;
#pragma unroll
            for (int nf = 0; nf < 4; nf++) {
                const int cc = bn + wn * 32 + nf * 8 + ec;
                *(float2*)(Cf + (size_t)r0 * N + cc)       = make_float2(acc[mf][nf][0], acc[mf][nf][1]);
                *(float2*)(Cf + (size_t)(r0 + 8) * N + cc) = make_float2(acc[mf][nf][2], acc[mf][nf][3]);
            }
        }
        return;
    }

    // MODE 4: per-tile dispatch
    const int nTile = bn >> 7;
    __half* Oh;
    const float* nw = nullptr;
    int Hh, head;
    bool donorm;
    if (nTile < 16)      { Oh = qf_o; nw = qw; Hh = HQ;  head = nTile;      donorm = true; }
    else if (nTile < 24) { Oh = kf_o; nw = kw; Hh = HKV; head = nTile - 16; donorm = true; }
    else                 { Oh = vf_o;          Hh = HKV; head = nTile - 24; donorm = false; }

    if (!donorm) {
#pragma unroll
        for (int mf = 0; mf < 4; mf++) {
            const int s0 = bm + wm * 64 + mf * 16 + er;
#pragma unroll
            for (int nf = 0; nf < 4; nf++) {
                const int col = wn * 32 + nf * 8 + ec;
#pragma unroll
                for (int h2i = 0; h2i < 2; h2i++) {
                    const int sg = s0 + h2i * 8;
                    __half2 h2 = __floats2half2_rn(acc[mf][nf][h2i * 2], acc[mf][nf][h2i * 2 + 1]);
                    *(__half2*)(Oh + ((size_t)sg * Hh + head) * D + col) = h2;
                }
            }
        }
        return;
    }

    float* xt  = (float*)smem;
    float* ssm = (float*)(smem + 128 * XT_STRIDE * 4);

#pragma unroll
    for (int mf = 0; mf < 4; mf++) {
        float s0 = 0.f, s1 = 0.f;
#pragma unroll
        for (int nf = 0; nf < 4; nf++) {
            s0 += acc[mf][nf][0] * acc[mf][nf][0] + acc[mf][nf][1] * acc[mf][nf][1];
            s1 += acc[mf][nf][2] * acc[mf][nf][2] + acc[mf][nf][3] * acc[mf][nf][3];
        }
        s0 += __shfl_xor_sync(0xffffffffu, s0, 1);
        s0 += __shfl_xor_sync(0xffffffffu, s0, 2);
        s1 += __shfl_xor_sync(0xffffffffu, s1, 1);
        s1 += __shfl_xor_sync(0xffffffffu, s1, 2);
        if ((lane & 3) == 0) {
            int r = wm * 64 + mf * 16 + er;
            ssm[r * 4 + wn]       = s0;
            ssm[(r + 8) * 4 + wn] = s1;
        }
    }
    __syncthreads();

    float wv2[8];
#pragma unroll
    for (int nf = 0; nf < 4; nf++) {
        wv2[nf * 2]     = nw[wn * 32 + nf * 8 + ec];
        wv2[nf * 2 + 1] = nw[wn * 32 + nf * 8 + ec + 1];
    }

#pragma unroll
    for (int mf = 0; mf < 4; mf++) {
        const int r0 = wm * 64 + mf * 16 + er, r1 = r0 + 8;
        float inv0 = rsqrtf((ssm[r0 * 4] + ssm[r0 * 4 + 1] + ssm[r0 * 4 + 2] + ssm[r0 * 4 + 3]) * (1.f / D) + 1e-6f);
        float inv1 = rsqrtf((ssm[r1 * 4] + ssm[r1 * 4 + 1] + ssm[r1 * 4 + 2] + ssm[r1 * 4 + 3]) * (1.f / D) + 1e-6f);
#pragma unroll
        for (int nf = 0; nf < 4; nf++) {
            const int col = wn * 32 + nf * 8 + ec;
            xt[r0 * XT_STRIDE + col]     = acc[mf][nf][0] * inv0 * wv2[nf * 2];
            xt[r0 * XT_STRIDE + col + 1] = acc[mf][nf][1] * inv0 * wv2[nf * 2 + 1];
            xt[r1 * XT_STRIDE + col]     = acc[mf][nf][2] * inv1 * wv2[nf * 2];
            xt[r1 * XT_STRIDE + col + 1] = acc[mf][nf][3] * inv1 * wv2[nf * 2 + 1];
        }
    }
    __syncthreads();

#pragma unroll
    for (int mf = 0; mf < 4; mf++) {
        const int rbase = wm * 64 + mf * 16 + er;
#pragma unroll
        for (int h2i = 0; h2i < 2; h2i++) {
            const int r = rbase + h2i * 8;
            const int sg = bm + r;
#pragma unroll
            for (int nf = 0; nf < 4; nf++) {
                const int col = wn * 32 + nf * 8 + ec;
                float x0 = xt[r * XT_STRIDE + col];
                float x1 = xt[r * XT_STRIDE + col + 1];
                float p0, p1;
                if (col < 64) {
                    p0 = -xt[r * XT_STRIDE + col + 64];
                    p1 = -xt[r * XT_STRIDE + col + 65];
                } else {
                    p0 = xt[r * XT_STRIDE + col - 64];
                    p1 = xt[r * XT_STRIDE + col - 63];
                }
                float c0 = cosp[(size_t)sg * D + col],     sn0 = sinp[(size_t)sg * D + col];
                float c1 = cosp[(size_t)sg * D + col + 1], sn1 = sinp[(size_t)sg * D + col + 1];
                float v0 = fmaf(x0, c0, p0 * sn0);
                float v1 = fmaf(x1, c1, p1 * sn1);
                *(__half2*)(Oh + ((size_t)sg * Hh + head) * D + col) = __floats2half2_rn(v0, v1);
            }
        }
    }
}

// ---------------------------------------------------------------------------
// MMA flash attention: 2 query-heads per CTA sharing one KV stream.
// 8 warps: warps 0-3 -> head 2y, warps 4-7 -> head 2y+1. 64 queries/CTA.
// ---------------------------------------------------------------------------
constexpr int AT_SMEM = 65536;   // 2 x 16KB KV stages + 2 x 16KB Q
constexpr float SCALE = 0.088388347648318447f;
constexpr float L2E   = 1.4426950408889634f;

__global__ __launch_bounds__(256, 2)
void attn_mma(const __half* __restrict__ Qf, const __half* __restrict__ Kf,
              const __half* __restrict__ Vf, __half* __restrict__ Out) {
    extern __shared__ char smem[];
    const uint32_t sb = smem_u32(smem);
    const int tid = threadIdx.x;
    const int w8 = tid >> 5, lane = tid & 31;
    const int hs = w8 >> 2;                 // head select 0/1
    const int w = w8 & 3;                   // warp within head group
    const int kvh = blockIdx.y;             // kv head 0..7
    const int h = kvh * 2 + hs;             // q head
    const int q0 = blockIdx.x * 64;

    const uint32_t QB = sb + 32768 + (uint32_t)hs * 16384;

    // stage Q for both heads: 2048 16B chunks, 8 per thread
#pragma unroll
    for (int i = 0; i < 8; i++) {
        int idx = tid + i * 256;
        int hd = idx >> 10;
        int rem = idx & 1023;
        int r = rem >> 4, c = rem & 15;
        const __half* src = Qf + ((size_t)(q0 + r) * HQ + kvh * 2 + hd) * D + c * 8;
        CP_ASYNC16(sb + 32768 + hd * 16384 + sw256(r, c), src);
    }
    CP_COMMIT();
    CP_WAIT0();
    __syncthreads();

    uint32_t qf[8][4];
    {
        const int arow = lane & 15, ahi = lane >> 4;
#pragma unroll
        for (int ks = 0; ks < 8; ks++) {
            uint32_t off = sw256(w * 16 + arow, 2 * ks + ahi);
            LDSM_X4(qf[ks][0], qf[ks][1], qf[ks][2], qf[ks][3], QB + off);
        }
    }

    float o[16][4];
#pragma unroll
    for (int nf = 0; nf < 16; nf++)
#pragma unroll
        for (int x = 0; x < 4; x++) o[nf][x] = 0.f;
    float m0 = 0.f, m1 = 0.f, l0 = 0.f, l1 = 0.f;

    int jlo = q0 - (WINDOW - 1);
    if (jlo < 0) jlo = 0;
    jlo &= ~31;
    const int NT = (q0 + 64 - jlo) >> 5;

    auto issue_kv = [&](int t) {
        const int j0 = jlo + t * 32;
        const uint32_t base = sb + (uint32_t)(t & 1) * 16384;
        const __half* srcs[2] = { Kf, Vf };
#pragma unroll
        for (int i = 0; i < 4; i++) {
            int idx = tid + i * 256;
            int ten = idx >> 9;
            int rem = idx & 511;
            int r = rem >> 4, c = rem & 15;
            const __half* src = srcs[ten] + ((size_t)(j0 + r) * HKV + kvh) * D + c * 8;
            CP_ASYNC16(base + ten * 8192 + sw256(r, c), src);
        }
        CP_COMMIT();
    };

    issue_kv(0);
    if (NT > 1) issue_kv(1);

    const int bnrow = (lane & 7) + ((lane >> 4) & 1) * 8;
    const int bhi = (lane >> 3) & 1;
    const int er = lane >> 2, ec = (lane & 3) * 2;
    const int r0g = q0 + w * 16 + er, r1g = r0g + 8;
    const int vg = lane >> 3, vr = lane & 7;

    for (int t = 0; t < NT; t++) {
        if (t < NT - 1) { CP_WAIT1(); } else { CP_WAIT0(); }
        __syncthreads();
        const int j0 = jlo + t * 32;
        const uint32_t base = sb + (uint32_t)(t & 1) * 16384;
        const uint32_t KB = base, VB = base + 8192;

        float s[4][4];
#pragma unroll
        for (int nf = 0; nf < 4; nf++)
#pragma unroll
            for (int x = 0; x < 4; x++) s[nf][x] = 0.f;
#pragma unroll
        for (int ks = 0; ks < 8; ks++) {
            uint32_t kf[2][4];
            const int ch = 2 * ks + bhi;
            LDSM_X4(kf[0][0], kf[0][1], kf[0][2], kf[0][3], KB + sw256(bnrow, ch));
            LDSM_X4(kf[1][0], kf[1][1], kf[1][2], kf[1][3], KB + sw256(16 + bnrow, ch));
#pragma unroll
            for (int nf = 0; nf < 4; nf++) {
                MMA_F16(s[nf], qf[ks], (&kf[nf >> 1][(nf & 1) * 2]));
            }
        }

        float mn0 = m0, mn1 = m1;
#pragma unroll
        for (int nf = 0; nf < 4; nf++) {
#pragma unroll
            for (int cx = 0; cx < 2; cx++) {
                const int jj = j0 + nf * 8 + ec + cx;
                s[nf][cx]     = (jj <= r0g && jj > r0g - WINDOW) ? s[nf][cx] * SCALE     : -1e9f;
                s[nf][2 + cx] = (jj <= r1g && jj > r1g - WINDOW) ? s[nf][2 + cx] * SCALE : -1e9f;
            }
            mn0 = fmaxf(mn0, fmaxf(s[nf][0], s[nf][1]));
            mn1 = fmaxf(mn1, fmaxf(s[nf][2], s[nf][3]));
        }
        mn0 = fmaxf(mn0, __shfl_xor_sync(0xffffffffu, mn0, 1));
        mn0 = fmaxf(mn0, __shfl_xor_sync(0xffffffffu, mn0, 2));
        mn1 = fmaxf(mn1, __shfl_xor_sync(0xffffffffu, mn1, 1));
        mn1 = fmaxf(mn1, __shfl_xor_sync(0xffffffffu, mn1, 2));
        const float a0 = exp2f((m0 - mn0) * L2E);
        const float a1 = exp2f((m1 - mn1) * L2E);
        m0 = mn0; m1 = mn1;

        float rs0 = 0.f, rs1 = 0.f;
        uint32_t ph[2][4];
#pragma unroll
        for (int kk = 0; kk < 2; kk++) {
            float p[2][4];
#pragma unroll
            for (int q2 = 0; q2 < 2; q2++) {
                const int nf = 2 * kk + q2;
                p[q2][0] = exp2f((s[nf][0] - m0) * L2E);
                p[q2][1] = exp2f((s[nf][1] - m0) * L2E);
                p[q2][2] = exp2f((s[nf][2] - m1) * L2E);
                p[q2][3] = exp2f((s[nf][3] - m1) * L2E);
                rs0 += p[q2][0] + p[q2][1];
                rs1 += p[q2][2] + p[q2][3];
            }
            ph[kk][0] = pack_h2(p[0][0], p[0][1]);
            ph[kk][1] = pack_h2(p[0][2], p[0][3]);
            ph[kk][2] = pack_h2(p[1][0], p[1][1]);
            ph[kk][3] = pack_h2(p[1][2], p[1][3]);
        }
        rs0 += __shfl_xor_sync(0xffffffffu, rs0, 1);
        rs0 += __shfl_xor_sync(0xffffffffu, rs0, 2);
        rs1 += __shfl_xor_sync(0xffffffffu, rs1, 1);
        rs1 += __shfl_xor_sync(0xffffffffu, rs1, 2);
        l0 = l0 * a0 + rs0;
        l1 = l1 * a1 + rs1;

#pragma unroll
        for (int nf = 0; nf < 16; nf++) {
            o[nf][0] *= a0; o[nf][1] *= a0;
            o[nf][2] *= a1; o[nf][3] *= a1;
        }

#pragma unroll
        for (int kk = 0; kk < 2; kk++) {
            const int vrow = kk * 16 + (vg & 1) * 8 + vr;
#pragma unroll
            for (int nc = 0; nc < 8; nc++) {
                uint32_t vf[4];
                LDSM_X4_T(vf[0], vf[1], vf[2], vf[3], VB + sw256(vrow, nc * 2 + (vg >> 1)));
                MMA_F16(o[nc * 2],     ph[kk], &vf[0]);
                MMA_F16(o[nc * 2 + 1], ph[kk], &vf[2]);
            }
        }
        __syncthreads();
        if (t + 2 < NT) issue_kv(t + 2);
    }

    const float i0 = 1.f / l0, i1 = 1.f / l1;
#pragma unroll
    for (int nf = 0; nf < 16; nf++) {
        const int cc = nf * 8 + ec;
        *(__half2*)(Out + ((size_t)r0g * HQ + h) * D + cc) = __floats2half2_rn(o[nf][0] * i0, o[nf][1] * i0);
        *(__half2*)(Out + ((size_t)r1g * HQ + h) * D + cc) = __floats2half2_rn(o[nf][2] * i1, o[nf][3] * i1);
    }
}

// ---------------------------------------------------------------------------
extern "C" void kernel_launch(void* const* d_in, const int* in_sizes, int n_in,
                              void* d_out, int out_size) {
    const float* hidden = (const float*)d_in[0];
    const float* cosp   = (const float*)d_in[1];
    const float* sinp   = (const float*)d_in[2];
    const float* Wq     = (const float*)d_in[3];
    const float* Wk     = (const float*)d_in[4];
    const float* Wv     = (const float*)d_in[5];
    const float* Wo     = (const float*)d_in[6];
    const float* qw     = (const float*)d_in[7];
    const float* kw     = (const float*)d_in[8];
    float* out = (float*)d_out;

    __half *hh, *wqkv, *wo, *ah, *qf, *kf, *vf;
    cudaGetSymbolAddress((void**)&hh,   g_hh);
    cudaGetSymbolAddress((void**)&wqkv, g_wqkv);
    cudaGetSymbolAddress((void**)&wo,   g_wo);
    cudaGetSymbolAddress((void**)&ah,   g_ah);
    cudaGetSymbolAddress((void**)&qf,   g_qf);
    cudaGetSymbolAddress((void**)&kf,   g_kf);
    cudaGetSymbolAddress((void**)&vf,   g_vf);

    cudaFuncSetAttribute(gemm_fused<0>, cudaFuncAttributeMaxDynamicSharedMemorySize, GEMM_SMEM);
    cudaFuncSetAttribute(gemm_fused<4>, cudaFuncAttributeMaxDynamicSharedMemorySize, GEMM_SMEM);
    cudaFuncSetAttribute(attn_mma, cudaFuncAttributeMaxDynamicSharedMemorySize, AT_SMEM);

    conv_all<<<CB_TOTAL, 256>>>(hidden, Wq, Wk, Wv, Wo, hh, wqkv, wo);

    const int NQKV = (HQ + 2 * HKV) * D;   // 4096
    gemm_fused<4><<<dim3(NQKV / 128, S / 128), 256, GEMM_SMEM>>>(
        hh, wqkv, nullptr, qf, kf, vf, qw, kw, cosp, sinp, NQKV, HID);

    attn_mma<<<dim3(S / 64, HKV), 256, AT_SMEM>>>(qf, kf, vf, ah);

    gemm_fused<0><<<dim3(HID / 128, S / 128), 256, GEMM_SMEM>>>(
        ah, wo, out, nullptr, nullptr, nullptr, nullptr, nullptr, nullptr, nullptr, HID, HQ * D);
}

// round 16
// speedup vs baseline: 1.0744x; 1.0744x over previous
#include <cuda_runtime.h>
#include <cuda_bf16.h>
#include <cuda_fp16.h>
#include <math.h>
#include <cstdint>

constexpr int S = 4096, HID = 2048, HQ = 16, HKV = 8, D = 128, WINDOW = 1024;

// fp16 operands
__device__ __half g_hh[(size_t)S * HID];
__device__ __half g_wqkv[(size_t)(HQ + 2 * HKV) * D * HID];   // [4096, 2048]
__device__ __half g_wo[(size_t)HID * HQ * D];
__device__ __half g_ah[(size_t)S * HQ * D];
__device__ __half g_qf[(size_t)S * HQ * D];
__device__ __half g_kf[(size_t)S * HKV * D];
__device__ __half g_vf[(size_t)S * HKV * D];

// ---------------------------------------------------------------------------
__device__ __forceinline__ uint32_t smem_u32(const void* p) {
    uint32_t a;
    asm("{ .reg .u64 t; cvta.to.shared.u64 t, %1; cvt.u32.u64 %0, t; }" : "=r"(a) : "l"(p));
    return a;
}
__device__ __forceinline__ uint32_t swz(uint32_t o) { return o ^ ((o >> 3) & 0x70); }
__device__ __forceinline__ uint32_t sw256(int r, int c) {
    return (uint32_t)(r * 256 + (((c ^ r) & 7) << 4) + ((c & 8) << 4));
}

#define CP_ASYNC16(dst, src) \
    asm volatile("cp.async.cg.shared.global [%0], [%1], 16;" :: "r"(dst), "l"(src))
#define CP_COMMIT() asm volatile("cp.async.commit_group;" ::: "memory")
#define CP_WAIT2()  asm volatile("cp.async.wait_group 2;" ::: "memory")
#define CP_WAIT1()  asm volatile("cp.async.wait_group 1;" ::: "memory")
#define CP_WAIT0()  asm volatile("cp.async.wait_group 0;" ::: "memory")

#define LDSM_X4(r0, r1, r2, r3, addr) \
    asm volatile("ldmatrix.sync.aligned.m8n8.x4.shared.b16 {%0,%1,%2,%3}, [%4];" \
                 : "=r"(r0), "=r"(r1), "=r"(r2), "=r"(r3) : "r"(addr))
#define LDSM_X4_T(r0, r1, r2, r3, addr) \
    asm volatile("ldmatrix.sync.aligned.m8n8.x4.trans.shared.b16 {%0,%1,%2,%3}, [%4];" \
                 : "=r"(r0), "=r"(r1), "=r"(r2), "=r"(r3) : "r"(addr))

#define MMA_F16(d, a, b) \
    asm volatile("mma.sync.aligned.m16n8k16.row.col.f32.f16.f16.f32 " \
                 "{%0,%1,%2,%3},{%4,%5,%6,%7},{%8,%9},{%0,%1,%2,%3};" \
                 : "+f"((d)[0]), "+f"((d)[1]), "+f"((d)[2]), "+f"((d)[3]) \
                 : "r"((a)[0]), "r"((a)[1]), "r"((a)[2]), "r"((a)[3]), \
                   "r"((b)[0]), "r"((b)[1]))

__device__ __forceinline__ uint32_t pack_h2(float a, float b) {
    __half2 t = __floats2half2_rn(a, b);
    return *(uint32_t*)&t;
}

// ---------------------------------------------------------------------------
// Single merged fp32->fp16 convert over all 5 tensors.
// ---------------------------------------------------------------------------
constexpr int CB_H  = 8192;
constexpr int CB_WQ = CB_H  + 4096;
constexpr int CB_WK = CB_WQ + 2048;
constexpr int CB_WV = CB_WK + 2048;
constexpr int CB_TOTAL = CB_WV + 4096;      // 20480 blocks

__global__ __launch_bounds__(256)
void conv_all(const float* __restrict__ hidden, const float* __restrict__ Wq,
              const float* __restrict__ Wk, const float* __restrict__ Wv,
              const float* __restrict__ Wo,
              __half* __restrict__ hh, __half* __restrict__ wqkv, __half* __restrict__ wo) {
    const int b = blockIdx.x;
    const float* src;
    __half* dst;
    int rel;
    if (b < CB_H)        { src = hidden; dst = hh;                          rel = b; }
    else if (b < CB_WQ)  { src = Wq;     dst = wqkv;                        rel = b - CB_H; }
    else if (b < CB_WK)  { src = Wk;     dst = wqkv + (size_t)HQ * D * HID; rel = b - CB_WQ; }
    else if (b < CB_WV)  { src = Wv;     dst = wqkv + (size_t)(HQ + HKV) * D * HID; rel = b - CB_WK; }
    else                 { src = Wo;     dst = wo;                          rel = b - CB_WV; }
    int i = (rel * 256 + threadIdx.x) * 4;
    float4 v = *(const float4*)(src + i);
    *(__half2*)(dst + i)     = __floats2half2_rn(v.x, v.y);
    *(__half2*)(dst + i + 2) = __floats2half2_rn(v.z, v.w);
}

// ---------------------------------------------------------------------------
// fp16 GEMM with fused epilogues, 3-stage pipeline, ONE barrier per chunk.
// MODE 0: plain fp32 C (Wo projection)
// MODE 4: QKV dispatch per 128-col tile: 0-15 Q norm+rope, 16-23 K norm+rope, 24-31 V conv
// ---------------------------------------------------------------------------
constexpr int TILE_BYTES = 128 * 64 * 2;
constexpr int BUF_BYTES  = 2 * TILE_BYTES;     // 32KB per stage
constexpr int NSTAGE     = 3;
constexpr int XT_STRIDE  = 132;
constexpr int GEMM_SMEM  = NSTAGE * BUF_BYTES; // 98304 >= epilogue 69632

template<int MODE>
__global__ __launch_bounds__(256, 2)
void gemm_fused(const __half* __restrict__ A, const __half* __restrict__ B,
                float* __restrict__ Cf,
                __half* __restrict__ qf_o, __half* __restrict__ kf_o, __half* __restrict__ vf_o,
                const float* __restrict__ qw, const float* __restrict__ kw,
                const float* __restrict__ cosp, const float* __restrict__ sinp,
                int N, int K) {
    extern __shared__ char smem[];
    const uint32_t sb = smem_u32(smem);
    const int tid = threadIdx.x;
    const int wid = tid >> 5;
    const int lane = tid & 31;
    const int wm = wid >> 2;
    const int wn = wid & 3;
    const int bm = blockIdx.y * 128;
    const int bn = blockIdx.x * 128;

    const __half* srcs[2] = { A, B };
    const int row0s[2] = { bm, bn };

    auto issue_copy = [&](int c) {
        const uint32_t base = sb + (uint32_t)(c % NSTAGE) * BUF_BYTES;
        const int k0 = c << 6;
#pragma unroll
        for (int t = 0; t < 2; t++) {
            const __half* src = srcs[t];
            const int row0 = row0s[t];
            const uint32_t tbase = base + t * TILE_BYTES;
#pragma unroll
            for (int i = 0; i < 4; i++) {
                int idx = tid + i * 256;
                int r  = idx >> 3;
                int cc = idx & 7;
                uint32_t dst = tbase + swz((uint32_t)(r * 128 + cc * 16));
                const void* s = src + (size_t)(row0 + r) * K + k0 + cc * 8;
                CP_ASYNC16(dst, s);
            }
        }
        CP_COMMIT();
    };

    float acc[4][4][4];
#pragma unroll
    for (int a = 0; a < 4; a++)
#pragma unroll
        for (int b = 0; b < 4; b++)
#pragma unroll
            for (int x = 0; x < 4; x++) acc[a][b][x] = 0.f;

    const int arow = (lane & 15);
    const int ahi  = lane >> 4;
    uint32_t a_rowoff[4];
#pragma unroll
    for (int mf = 0; mf < 4; mf++)
        a_rowoff[mf] = (uint32_t)((wm * 64 + mf * 16 + arow) * 128);
    const uint32_t arx = (uint32_t)(arow & 7);

    const int bnrow = (lane & 7) + ((lane >> 4) & 1) * 8;
    const int bhi   = (lane >> 3) & 1;
    uint32_t b_rowoff[2];
#pragma unroll
    for (int bf = 0; bf < 2; bf++)
        b_rowoff[bf] = (uint32_t)((wn * 32 + bf * 16 + bnrow) * 128);
    const uint32_t brx = (uint32_t)(bnrow & 7);

    const int NC = K >> 6;
    issue_copy(0);
    if (NC > 1) issue_copy(1);
    if (NC > 2) issue_copy(2);

    for (int c = 0; c < NC; c++) {
        // wait for chunk c
        if (c == 0) {
            if (NC > 2) { CP_WAIT2(); } else if (NC > 1) { CP_WAIT1(); } else { CP_WAIT0(); }
        } else if (c < NC - 1) {
            CP_WAIT1();
        } else {
            CP_WAIT0();
        }
        __syncthreads();    // chunk c visible AND buffer (c+2)%3 free (consumed in iter c-1)
        if (c >= 1 && c + 2 < NC) issue_copy(c + 2);

        const uint32_t base = sb + (uint32_t)(c % NSTAGE) * BUF_BYTES;
        const uint32_t A_b = base;
        const uint32_t B_b = base + TILE_BYTES;

#pragma unroll
        for (int ks = 0; ks < 4; ks++) {
            uint32_t ah[4][4], bh[2][4];
            const uint32_t ac = (uint32_t)(ks * 2 + ahi);
            const uint32_t bc = (uint32_t)(ks * 2 + bhi);
#pragma unroll
            for (int mf = 0; mf < 4; mf++) {
                uint32_t off = a_rowoff[mf] + ((ac ^ arx) << 4);
                LDSM_X4(ah[mf][0], ah[mf][1], ah[mf][2], ah[mf][3], A_b + off);
            }
#pragma unroll
            for (int bf = 0; bf < 2; bf++) {
                uint32_t off = b_rowoff[bf] + ((bc ^ brx) << 4);
                LDSM_X4(bh[bf][0], bh[bf][1], bh[bf][2], bh[bf][3], B_b + off);
            }
#pragma unroll
            for (int mf = 0; mf < 4; mf++)
#pragma unroll
                for (int nf = 0; nf < 4; nf++) {
                    MMA_F16(acc[mf][nf], ah[mf], (&bh[nf >> 1][(nf & 1) * 2]));
                }
        }
    }
    __syncthreads();   // before epilogue reuses smem

    const int er = lane >> 2;
    const int ec = (lane & 3) * 2;

    if (MODE == 0) {
#pragma unroll
        for (int mf = 0; mf < 4; mf++) {
            const int r0 = bm + wm * 64 + mf * 16 + er;
#pragma unroll
            for (int nf = 0; nf < 4; nf++) {
                const int cc = bn + wn * 32 + nf * 8 + ec;
                *(float2*)(Cf + (size_t)r0 * N + cc)       = make_float2(acc[mf][nf][0], acc[mf][nf][1]);
                *(float2*)(Cf + (size_t)(r0 + 8) * N + cc) = make_float2(acc[mf][nf][2], acc[mf][nf][3]);
            }
        }
        return;
    }

    // MODE 4: per-tile dispatch
    const int nTile = bn >> 7;
    __half* Oh;
    const float* nw = nullptr;
    int Hh, head;
    bool donorm;
    if (nTile < 16)      { Oh = qf_o; nw = qw; Hh = HQ;  head = nTile;      donorm = true; }
    else if (nTile < 24) { Oh = kf_o; nw = kw; Hh = HKV; head = nTile - 16; donorm = true; }
    else                 { Oh = vf_o;          Hh = HKV; head = nTile - 24; donorm = false; }

    if (!donorm) {
#pragma unroll
        for (int mf = 0; mf < 4; mf++) {
            const int s0 = bm + wm * 64 + mf * 16 + er;
#pragma unroll
            for (int nf = 0; nf < 4; nf++) {
                const int col = wn * 32 + nf * 8 + ec;
#pragma unroll
                for (int h2i = 0; h2i < 2; h2i++) {
                    const int sg = s0 + h2i * 8;
                    __half2 h2 = __floats2half2_rn(acc[mf][nf][h2i * 2], acc[mf][nf][h2i * 2 + 1]);
                    *(__half2*)(Oh + ((size_t)sg * Hh + head) * D + col) = h2;
                }
            }
        }
        return;
    }

    // RMSNorm + RoPE
    float* xt  = (float*)smem;
    float* ssm = (float*)(smem + 128 * XT_STRIDE * 4);

#pragma unroll
    for (int mf = 0; mf < 4; mf++) {
        float s0 = 0.f, s1 = 0.f;
#pragma unroll
        for (int nf = 0; nf < 4; nf++) {
            s0 += acc[mf][nf][0] * acc[mf][nf][0] + acc[mf][nf][1] * acc[mf][nf][1];
            s1 += acc[mf][nf][2] * acc[mf][nf][2] + acc[mf][nf][3] * acc[mf][nf][3];
        }
        s0 += __shfl_xor_sync(0xffffffffu, s0, 1);
        s0 += __shfl_xor_sync(0xffffffffu, s0, 2);
        s1 += __shfl_xor_sync(0xffffffffu, s1, 1);
        s1 += __shfl_xor_sync(0xffffffffu, s1, 2);
        if ((lane & 3) == 0) {
            int r = wm * 64 + mf * 16 + er;
            ssm[r * 4 + wn]       = s0;
            ssm[(r + 8) * 4 + wn] = s1;
        }
    }
    __syncthreads();

    float wv2[8];
#pragma unroll
    for (int nf = 0; nf < 4; nf++) {
        wv2[nf * 2]     = nw[wn * 32 + nf * 8 + ec];
        wv2[nf * 2 + 1] = nw[wn * 32 + nf * 8 + ec + 1];
    }

#pragma unroll
    for (int mf = 0; mf < 4; mf++) {
        const int r0 = wm * 64 + mf * 16 + er, r1 = r0 + 8;
        float inv0 = rsqrtf((ssm[r0 * 4] + ssm[r0 * 4 + 1] + ssm[r0 * 4 + 2] + ssm[r0 * 4 + 3]) * (1.f / D) + 1e-6f);
        float inv1 = rsqrtf((ssm[r1 * 4] + ssm[r1 * 4 + 1] + ssm[r1 * 4 + 2] + ssm[r1 * 4 + 3]) * (1.f / D) + 1e-6f);
#pragma unroll
        for (int nf = 0; nf < 4; nf++) {
            const int col = wn * 32 + nf * 8 + ec;
            xt[r0 * XT_STRIDE + col]     = acc[mf][nf][0] * inv0 * wv2[nf * 2];
            xt[r0 * XT_STRIDE + col + 1] = acc[mf][nf][1] * inv0 * wv2[nf * 2 + 1];
            xt[r1 * XT_STRIDE + col]     = acc[mf][nf][2] * inv1 * wv2[nf * 2];
            xt[r1 * XT_STRIDE + col + 1] = acc[mf][nf][3] * inv1 * wv2[nf * 2 + 1];
        }
    }
    __syncthreads();

#pragma unroll
    for (int mf = 0; mf < 4; mf++) {
        const int rbase = wm * 64 + mf * 16 + er;
#pragma unroll
        for (int h2i = 0; h2i < 2; h2i++) {
            const int r = rbase + h2i * 8;
            const int sg = bm + r;
#pragma unroll
            for (int nf = 0; nf < 4; nf++) {
                const int col = wn * 32 + nf * 8 + ec;
                float x0 = xt[r * XT_STRIDE + col];
                float x1 = xt[r * XT_STRIDE + col + 1];
                float p0, p1;
                if (col < 64) {
                    p0 = -xt[r * XT_STRIDE + col + 64];
                    p1 = -xt[r * XT_STRIDE + col + 65];
                } else {
                    p0 = xt[r * XT_STRIDE + col - 64];
                    p1 = xt[r * XT_STRIDE + col - 63];
                }
                float c0 = cosp[(size_t)sg * D + col],     sn0 = sinp[(size_t)sg * D + col];
                float c1 = cosp[(size_t)sg * D + col + 1], sn1 = sinp[(size_t)sg * D + col + 1];
                float v0 = fmaf(x0, c0, p0 * sn0);
                float v1 = fmaf(x1, c1, p1 * sn1);
                *(__half2*)(Oh + ((size_t)sg * Hh + head) * D + col) = __floats2half2_rn(v0, v1);
            }
        }
    }
}

// ---------------------------------------------------------------------------
// MMA flash attention (round-13 version): plain fp16, 128 threads, occ 2.
// ---------------------------------------------------------------------------
constexpr int AT_SMEM = 49152;
constexpr float SCALE = 0.088388347648318447f;
constexpr float L2E   = 1.4426950408889634f;

__global__ __launch_bounds__(128, 2)
void attn_mma(const __half* __restrict__ Qf, const __half* __restrict__ Kf,
              const __half* __restrict__ Vf, __half* __restrict__ Out) {
    extern __shared__ char smem[];
    const uint32_t sb = smem_u32(smem);
    const int tid = threadIdx.x;
    const int w = tid >> 5, lane = tid & 31;
    const int h = blockIdx.y, kvh = h >> 1;
    const int q0 = blockIdx.x * 64;

    const uint32_t QB = sb + 32768;

#pragma unroll
    for (int i = 0; i < 8; i++) {
        int idx = tid + i * 128;
        int r = idx >> 4, c = idx & 15;
        const __half* src = Qf + ((size_t)(q0 + r) * HQ + h) * D + c * 8;
        CP_ASYNC16(QB + sw256(r, c), src);
    }
    CP_COMMIT();
    CP_WAIT0();
    __syncthreads();

    uint32_t qf[8][4];
    {
        const int arow = lane & 15, ahi = lane >> 4;
#pragma unroll
        for (int ks = 0; ks < 8; ks++) {
            uint32_t off = sw256(w * 16 + arow, 2 * ks + ahi);
            LDSM_X4(qf[ks][0], qf[ks][1], qf[ks][2], qf[ks][3], QB + off);
        }
    }

    float o[16][4];
#pragma unroll
    for (int nf = 0; nf < 16; nf++)
#pragma unroll
        for (int x = 0; x < 4; x++) o[nf][x] = 0.f;
    float m0 = 0.f, m1 = 0.f, l0 = 0.f, l1 = 0.f;

    int jlo = q0 - (WINDOW - 1);
    if (jlo < 0) jlo = 0;
    jlo &= ~31;
    const int NT = (q0 + 64 - jlo) >> 5;

    auto issue_kv = [&](int t) {
        const int j0 = jlo + t * 32;
        const uint32_t base = sb + (uint32_t)(t & 1) * 16384;
        const __half* srcs[2] = { Kf, Vf };
#pragma unroll
        for (int i = 0; i < 8; i++) {
            int idx = tid + i * 128;
            int ten = idx >> 9;
            int rem = idx & 511;
            int r = rem >> 4, c = rem & 15;
            const __half* src = srcs[ten] + ((size_t)(j0 + r) * HKV + kvh) * D + c * 8;
            CP_ASYNC16(base + ten * 8192 + sw256(r, c), src);
        }
        CP_COMMIT();
    };

    issue_kv(0);
    if (NT > 1) issue_kv(1);

    const int bnrow = (lane & 7) + ((lane >> 4) & 1) * 8;
    const int bhi = (lane >> 3) & 1;
    const int er = lane >> 2, ec = (lane & 3) * 2;
    const int r0g = q0 + w * 16 + er, r1g = r0g + 8;
    const int vg = lane >> 3, vr = lane & 7;

    for (int t = 0; t < NT; t++) {
        if (t < NT - 1) { CP_WAIT1(); } else { CP_WAIT0(); }
        __syncthreads();
        const int j0 = jlo + t * 32;
        const uint32_t base = sb + (uint32_t)(t & 1) * 16384;
        const uint32_t KB = base, VB = base + 8192;

        float s[4][4];
#pragma unroll
        for (int nf = 0; nf < 4; nf++)
#pragma unroll
            for (int x = 0; x < 4; x++) s[nf][x] = 0.f;
#pragma unroll
        for (int ks = 0; ks < 8; ks++) {
            uint32_t kf[2][4];
            const int ch = 2 * ks + bhi;
            LDSM_X4(kf[0][0], kf[0][1], kf[0][2], kf[0][3], KB + sw256(bnrow, ch));
            LDSM_X4(kf[1][0], kf[1][1], kf[1][2], kf[1][3], KB + sw256(16 + bnrow, ch));
#pragma unroll
            for (int nf = 0; nf < 4; nf++) {
                MMA_F16(s[nf], qf[ks], (&kf[nf >> 1][(nf & 1) * 2]));
            }
        }

        float mn0 = m0, mn1 = m1;
#pragma unroll
        for (int nf = 0; nf < 4; nf++) {
#pragma unroll
            for (int cx = 0; cx < 2; cx++) {
                const int jj = j0 + nf * 8 + ec + cx;
                s[nf][cx]     = (jj <= r0g && jj > r0g - WINDOW) ? s[nf][cx] * SCALE     : -1e9f;
                s[nf][2 + cx] = (jj <= r1g && jj > r1g - WINDOW) ? s[nf][2 + cx] * SCALE : -1e9f;
            }
            mn0 = fmaxf(mn0, fmaxf(s[nf][0], s[nf][1]));
            mn1 = fmaxf(mn1, fmaxf(s[nf][2], s[nf][3]));
        }
        mn0 = fmaxf(mn0, __shfl_xor_sync(0xffffffffu, mn0, 1));
        mn0 = fmaxf(mn0, __shfl_xor_sync(0xffffffffu, mn0, 2));
        mn1 = fmaxf(mn1, __shfl_xor_sync(0xffffffffu, mn1, 1));
        mn1 = fmaxf(mn1, __shfl_xor_sync(0xffffffffu, mn1, 2));
        const float a0 = exp2f((m0 - mn0) * L2E);
        const float a1 = exp2f((m1 - mn1) * L2E);
        m0 = mn0; m1 = mn1;

        float rs0 = 0.f, rs1 = 0.f;
        uint32_t ph[2][4];
#pragma unroll
        for (int kk = 0; kk < 2; kk++) {
            float p[2][4];
#pragma unroll
            for (int q2 = 0; q2 < 2; q2++) {
                const int nf = 2 * kk + q2;
                p[q2][0] = exp2f((s[nf][0] - m0) * L2E);
                p[q2][1] = exp2f((s[nf][1] - m0) * L2E);
                p[q2][2] = exp2f((s[nf][2] - m1) * L2E);
                p[q2][3] = exp2f((s[nf][3] - m1) * L2E);
                rs0 += p[q2][0] + p[q2][1];
                rs1 += p[q2][2] + p[q2][3];
            }
            ph[kk][0] = pack_h2(p[0][0], p[0][1]);
            ph[kk][1] = pack_h2(p[0][2], p[0][3]);
            ph[kk][2] = pack_h2(p[1][0], p[1][1]);
            ph[kk][3] = pack_h2(p[1][2], p[1][3]);
        }
        rs0 += __shfl_xor_sync(0xffffffffu, rs0, 1);
        rs0 += __shfl_xor_sync(0xffffffffu, rs0, 2);
        rs1 += __shfl_xor_sync(0xffffffffu, rs1, 1);
        rs1 += __shfl_xor_sync(0xffffffffu, rs1, 2);
        l0 = l0 * a0 + rs0;
        l1 = l1 * a1 + rs1;

#pragma unroll
        for (int nf = 0; nf < 16; nf++) {
            o[nf][0] *= a0; o[nf][1] *= a0;
            o[nf][2] *= a1; o[nf][3] *= a1;
        }

#pragma unroll
        for (int kk = 0; kk < 2; kk++) {
            const int vrow = kk * 16 + (vg & 1) * 8 + vr;
#pragma unroll
            for (int nc = 0; nc < 8; nc++) {
                uint32_t vf[4];
                LDSM_X4_T(vf[0], vf[1], vf[2], vf[3], VB + sw256(vrow, nc * 2 + (vg >> 1)));
                MMA_F16(o[nc * 2],     ph[kk], &vf[0]);
                MMA_F16(o[nc * 2 + 1], ph[kk], &vf[2]);
            }
        }
        __syncthreads();
        if (t + 2 < NT) issue_kv(t + 2);
    }

    const float i0 = 1.f / l0, i1 = 1.f / l1;
#pragma unroll
    for (int nf = 0; nf < 16; nf++) {
        const int cc = nf * 8 + ec;
        *(__half2*)(Out + ((size_t)r0g * HQ + h) * D + cc) = __floats2half2_rn(o[nf][0] * i0, o[nf][1] * i0);
        *(__half2*)(Out + ((size_t)r1g * HQ + h) * D + cc) = __floats2half2_rn(o[nf][2] * i1, o[nf][3] * i1);
    }
}

// ---------------------------------------------------------------------------
extern "C" void kernel_launch(void* const* d_in, const int* in_sizes, int n_in,
                              void* d_out, int out_size) {
    const float* hidden = (const float*)d_in[0];
    const float* cosp   = (const float*)d_in[1];
    const float* sinp   = (const float*)d_in[2];
    const float* Wq     = (const float*)d_in[3];
    const float* Wk     = (const float*)d_in[4];
    const float* Wv     = (const float*)d_in[5];
    const float* Wo     = (const float*)d_in[6];
    const float* qw     = (const float*)d_in[7];
    const float* kw     = (const float*)d_in[8];
    float* out = (float*)d_out;

    __half *hh, *wqkv, *wo, *ah, *qf, *kf, *vf;
    cudaGetSymbolAddress((void**)&hh,   g_hh);
    cudaGetSymbolAddress((void**)&wqkv, g_wqkv);
    cudaGetSymbolAddress((void**)&wo,   g_wo);
    cudaGetSymbolAddress((void**)&ah,   g_ah);
    cudaGetSymbolAddress((void**)&qf,   g_qf);
    cudaGetSymbolAddress((void**)&kf,   g_kf);
    cudaGetSymbolAddress((void**)&vf,   g_vf);

    cudaFuncSetAttribute(gemm_fused<0>, cudaFuncAttributeMaxDynamicSharedMemorySize, GEMM_SMEM);
    cudaFuncSetAttribute(gemm_fused<4>, cudaFuncAttributeMaxDynamicSharedMemorySize, GEMM_SMEM);
    cudaFuncSetAttribute(attn_mma, cudaFuncAttributeMaxDynamicSharedMemorySize, AT_SMEM);

    conv_all<<<CB_TOTAL, 256>>>(hidden, Wq, Wk, Wv, Wo, hh, wqkv, wo);

    const int NQKV = (HQ + 2 * HKV) * D;   // 4096
    gemm_fused<4><<<dim3(NQKV / 128, S / 128), 256, GEMM_SMEM>>>(
        hh, wqkv, nullptr, qf, kf, vf, qw, kw, cosp, sinp, NQKV, HID);

    attn_mma<<<dim3(S / 64, HQ), 128, AT_SMEM>>>(qf, kf, vf, ah);

    gemm_fused<0><<<dim3(HID / 128, S / 128), 256, GEMM_SMEM>>>(
        ah, wo, out, nullptr, nullptr, nullptr, nullptr, nullptr, nullptr, nullptr, HID, HQ * D);
}